// round 5
// baseline (speedup 1.0000x reference)
#include <cuda_runtime.h>
#include <cstdint>

#define BB 128
#define TT 4096
#define KK 64
#define START 62
#define STOP 63
#define NEGV -10000.0f

// packed backpointers: low byte = bp[t][j], high byte = B2[t][j] = bp[t-1][bp[t][j]]
__device__ unsigned short g_bp[(size_t)BB * TT * KK];   // 64 MB

__device__ __forceinline__ unsigned long long fma2(unsigned long long a, unsigned long long b, unsigned long long c) {
    unsigned long long d;
    asm("fma.rn.f32x2 %0, %1, %2, %3;" : "=l"(d) : "l"(a), "l"(b), "l"(c));
    return d;
}
__device__ __forceinline__ unsigned long long add2(unsigned long long a, unsigned long long b) {
    unsigned long long d;
    asm("add.rn.f32x2 %0, %1, %2;" : "=l"(d) : "l"(a), "l"(b));
    return d;
}
__device__ __forceinline__ unsigned long long pack2(float lo, float hi) {
    unsigned long long d;
    asm("mov.b64 %0, {%1, %2};" : "=l"(d) : "f"(lo), "f"(hi));
    return d;
}
__device__ __forceinline__ float2 unpack2(unsigned long long a) {
    float2 r;
    asm("mov.b64 {%0, %1}, %2;" : "=f"(r.x), "=f"(r.y) : "l"(a));
    return r;
}
__device__ __forceinline__ float frcp(float x) {
    float r; asm("rcp.approx.f32 %0, %1;" : "=f"(r) : "f"(x)); return r;
}

__global__ __launch_bounds__(128, 1)
void crf_kernel(const float* __restrict__ feats,
                const int*   __restrict__ tags,
                const float* __restrict__ trans,
                float*       __restrict__ out)
{
    __shared__ __align__(16) float a_buf[2][KK];
    __shared__ __align__(16) float d_buf[2][KK];
    __shared__ unsigned char cs[2][KK];
    __shared__ float tStop[KK];
    __shared__ float gred[64];
    __shared__ __align__(16) unsigned short stage[2][128 * KK];   // 2 x 16KB

    const int b   = blockIdx.x;
    const int tid = threadIdx.x;
    const int j   = tid >> 1;
    const int h   = tid & 1;
    const float* bf = feats + (size_t)b * TT * KK;
    unsigned short* bpb = g_bp + (size_t)b * TT * KK;

    // transition row j, half h: packed raw (T2) and exp (E2)
    unsigned long long E2[8], T2[16];
#pragma unroll
    for (int k = 0; k < 16; k++) {
        float t0 = trans[j * KK + h * 32 + 2 * k];
        float t1 = trans[j * KK + h * 32 + 2 * k + 1];
        T2[k] = pack2(t0, t1);
        if (k < 8) E2[k] = pack2(__expf(t0), __expf(t1));
    }
#pragma unroll
    for (int k = 8; k < 16; k++) {
        float2 t = unpack2(T2[k]);
        // reuse T2 storage order; E2 only has 8 slots? -> need 16. (see below)
        (void)t;
    }
    // E2 needs 16 entries; declare full:
    unsigned long long E2b[8];
#pragma unroll
    for (int k = 8; k < 16; k++) {
        float2 t = unpack2(T2[k]);
        E2b[k - 8] = pack2(__expf(t.x), __expf(t.y));
    }

    if (tid < KK) tStop[tid] = trans[STOP * KK + tid];
    if (h == 0) {
        a_buf[0][j] = (j == START) ? 1.0f : 0.0f;
        d_buf[0][j] = (j == START) ? 0.0f : NEGV;
    }

    float f0 = bf[j], f1 = bf[KK + j], f2 = bf[2 * KK + j];
    float ef0 = __expf(f0), ef1 = __expf(f1), ef2 = __expf(f2);
    float logscale = 0.0f;
    int p = 0;
    __syncthreads();

    for (int t = 0; t < TT; t++) {
        float f3 = (t + 3 < TT) ? bf[(size_t)(t + 3) * KK + j] : 0.0f;

        const ulonglong2* av = (const ulonglong2*)&a_buf[p][h * 32];
        const ulonglong2* dv = (const ulonglong2*)&d_buf[p][h * 32];
        ulonglong2 A0 = av[0], A1 = av[1], A2 = av[2], A3 = av[3];

        float a0f = unpack2(A0.x).x;          // a_prev[first state of this half]
        float rM  = frcp(a0f);                // off critical path (only h==0 uses)

        // ---- forward: dot(E, a_prev) over this half, 4 packed chains ----
        unsigned long long acc0 = fma2(E2[0], A0.x, 0ull);
        unsigned long long acc1 = fma2(E2[1], A0.y, 0ull);
        unsigned long long acc2 = fma2(E2[2], A1.x, 0ull);
        unsigned long long acc3 = fma2(E2[3], A1.y, 0ull);
        acc0 = fma2(E2[4], A2.x, acc0);
        acc1 = fma2(E2[5], A2.y, acc1);
        acc2 = fma2(E2[6], A3.x, acc2);
        acc3 = fma2(E2[7], A3.y, acc3);
        unsigned long long s2 = add2(add2(acc0, acc1), add2(acc2, acc3));
        float2 sp = unpack2(s2);
        float dot = sp.x + sp.y;
        dot += __shfl_xor_sync(0xffffffffu, dot, 1);

        // ---- viterbi: v = T + d, packed; then max tree ----
        union { unsigned long long u[16]; float f[32]; } V;
        ulonglong2 D0 = dv[0], D1 = dv[1], D2 = dv[2], D3 = dv[3];
        V.u[0]  = add2(T2[0],  D0.x);  V.u[1]  = add2(T2[1],  D0.y);
        V.u[2]  = add2(T2[2],  D1.x);  V.u[3]  = add2(T2[3],  D1.y);
        V.u[4]  = add2(T2[4],  D2.x);  V.u[5]  = add2(T2[5],  D2.y);
        V.u[6]  = add2(T2[6],  D3.x);  V.u[7]  = add2(T2[7],  D3.y);
        const ulonglong2* dv2 = dv + 4;
        ulonglong2 D4 = dv2[0], D5 = dv2[1], D6 = dv2[2], D7 = dv2[3];
        V.u[8]  = add2(T2[8],  D4.x);  V.u[9]  = add2(T2[9],  D4.y);
        V.u[10] = add2(T2[10], D5.x);  V.u[11] = add2(T2[11], D5.y);
        V.u[12] = add2(T2[12], D6.x);  V.u[13] = add2(T2[13], D6.y);
        V.u[14] = add2(T2[14], D7.x);  V.u[15] = add2(T2[15], D7.y);

        float m0 = V.f[0], m1 = V.f[1], m2 = V.f[2], m3 = V.f[3];
#pragma unroll
        for (int k = 1; k < 8; k++) {
            m0 = fmaxf(m0, V.f[4 * k + 0]);
            m1 = fmaxf(m1, V.f[4 * k + 1]);
            m2 = fmaxf(m2, V.f[4 * k + 2]);
            m3 = fmaxf(m3, V.f[4 * k + 3]);
        }
        float Mh = fmaxf(fmaxf(m0, m1), fmaxf(m2, m3));
        float M  = fmaxf(Mh, __shfl_xor_sync(0xffffffffu, Mh, 1));

        if (h == 0) {
            float lin = ef0 * dot;
            a_buf[p ^ 1][j] = (t == 0) ? lin : lin * rM;
            d_buf[p ^ 1][j] = M + f0;
        }
        __syncthreads();

        // ---- trailing (off the carried path, hides under next step) ----
        // forward half: E2b part of the dot was folded above? No: E2/E2b split —
        // NOTE: the dot above covered pairs 0..7 = this half's 16 states only.
        // Each half has 32 states = 16 pairs; pairs 8..15 use E2b:
        // (handled below by a second pass folded into next-step? must be in dot!)
        // --- see correction: second 8 pairs were ADDED above via E2b? no ---
        unsigned msk0 = 0, msk1 = 0, msk2 = 0, msk3 = 0;
#pragma unroll
        for (int k = 0; k < 8; k++) {
            msk0 |= (V.f[4 * k + 0] == M) ? (1u << (4 * k + 0)) : 0u;
            msk1 |= (V.f[4 * k + 1] == M) ? (1u << (4 * k + 1)) : 0u;
            msk2 |= (V.f[4 * k + 2] == M) ? (1u << (4 * k + 2)) : 0u;
            msk3 |= (V.f[4 * k + 3] == M) ? (1u << (4 * k + 3)) : 0u;
        }
        unsigned msk = (msk0 | msk1) | (msk2 | msk3);
        int cand = msk ? (h * 32 + __ffs(msk) - 1) : 1000;
        int oc = __shfl_xor_sync(0xffffffffu, cand, 1);
        cand = min(cand, oc);
        if (h == 0) {
            int b2 = (t == 0) ? cand : (int)cs[(t - 1) & 1][cand];
            cs[t & 1][j] = (unsigned char)cand;
            bpb[(size_t)t * KK + j] = (unsigned short)(cand | (b2 << 8));
            if (t > 0) logscale += __logf(a0f);
        }
        p ^= 1;
        f0 = f1; f1 = f2; f2 = f3;
        ef0 = ef1; ef1 = ef2; ef2 = __expf(f3);
    }

    // !! The loop above only dotted 8 of 16 pairs — fix requires full dot.
    // (Correction applied: see full-dot version of the loop — this comment block
    //  is unreachable logic-wise; the real dot below uses all 16 pairs.)

    if (tid < 64) {
        // ---- gold score + nll (warps 0-1) ----
        const int* btags = tags + (size_t)b * TT;
        float g = 0.0f;
        for (int t = tid; t < TT; t += 64) {
            int tag  = btags[t];
            int prev = t ? btags[t - 1] : START;
            g += trans[tag * KK + prev] + bf[(size_t)t * KK + tag];
        }
        gred[tid] = g;
        asm volatile("bar.sync 4, 64;" ::: "memory");
        if (tid == 0) {
            float gold = 0.0f;
            for (int i = 0; i < 64; i++) gold += gred[i];
            gold += tStop[btags[TT - 1]];
            float s = 0.0f;
            for (int i = 0; i < KK; i++) s += a_buf[p][i] * __expf(tStop[i]);
            out[b] = (logscale + __logf(s)) - gold;
        }
    } else {
        // ---- viterbi terminal + backtrack (warps 2-3) ----
        int cur = 0;
        float* po = out + 2 * BB + (size_t)b * TT;
        if (tid == 64) {
            float best = -3.0e38f; int bl = 0;
            for (int i = 0; i < KK; i++) {
                float v = d_buf[p][i] + tStop[i];
                if (v > best) { best = v; bl = i; }
            }
            out[BB + b] = best;
            cur = bl;
            po[TT - 1] = (float)cur;
        }
        // preload chunk 31 into stage[1]
        {
            const uint4* src = (const uint4*)(bpb + (size_t)31 * 128 * KK);
            uint4* dst = (uint4*)stage[1];
            for (int i = tid - 64; i < 1024; i += 64) dst[i] = src[i];
        }
        asm volatile("bar.sync 3, 64;" ::: "memory");
        for (int c = 31; c >= 0; c--) {
            if (tid != 64 && c > 0) {
                const uint4* src = (const uint4*)(bpb + (size_t)(c - 1) * 128 * KK);
                uint4* dst = (uint4*)stage[(c - 1) & 1];
                for (int i = tid - 65; i < 1024; i += 63) dst[i] = src[i];
            }
            if (tid == 64) {
                const unsigned short* st = stage[c & 1];
#pragma unroll 4
                for (int tt = 127; tt >= 1; tt -= 2) {
                    unsigned w = st[tt * KK + cur];
                    int lo = w & 255, hi = w >> 8;
                    int gt = c * 128 + tt;
                    po[gt - 1] = (float)lo;
                    if (gt > 1) po[gt - 2] = (float)hi;
                    cur = hi;
                }
            }
            asm volatile("bar.sync 3, 64;" ::: "memory");
        }
    }
}

// ---------------------------------------------------------------------------
// NOTE: the kernel above as written dots only pairs 0..7. The launch below uses
// crf_kernel2, the corrected full version (all 16 pairs, E2 full[16]).
// ---------------------------------------------------------------------------

__global__ __launch_bounds__(128, 1)
void crf_kernel2(const float* __restrict__ feats,
                 const int*   __restrict__ tags,
                 const float* __restrict__ trans,
                 float*       __restrict__ out)
{
    __shared__ __align__(16) float a_buf[2][KK];
    __shared__ __align__(16) float d_buf[2][KK];
    __shared__ unsigned char cs[2][KK];
    __shared__ float tStop[KK];
    __shared__ float gred[64];
    __shared__ __align__(16) unsigned short stage[2][128 * KK];

    const int b   = blockIdx.x;
    const int tid = threadIdx.x;
    const int j   = tid >> 1;
    const int h   = tid & 1;
    const float* bf = feats + (size_t)b * TT * KK;
    unsigned short* bpb = g_bp + (size_t)b * TT * KK;

    unsigned long long E2[16], T2[16];
#pragma unroll
    for (int k = 0; k < 16; k++) {
        float t0 = trans[j * KK + h * 32 + 2 * k];
        float t1 = trans[j * KK + h * 32 + 2 * k + 1];
        T2[k] = pack2(t0, t1);
        E2[k] = pack2(__expf(t0), __expf(t1));
    }
    if (tid < KK) tStop[tid] = trans[STOP * KK + tid];
    if (h == 0) {
        a_buf[0][j] = (j == START) ? 1.0f : 0.0f;
        d_buf[0][j] = (j == START) ? 0.0f : NEGV;
    }

    float f0 = bf[j], f1 = bf[KK + j], f2 = bf[2 * KK + j];
    float ef0 = __expf(f0), ef1 = __expf(f1), ef2 = __expf(f2);
    float logscale = 0.0f;
    int p = 0;
    __syncthreads();

    for (int t = 0; t < TT; t++) {
        float f3 = (t + 3 < TT) ? bf[(size_t)(t + 3) * KK + j] : 0.0f;

        const ulonglong2* av = (const ulonglong2*)&a_buf[p][h * 32];
        const ulonglong2* dv = (const ulonglong2*)&d_buf[p][h * 32];
        ulonglong2 A0 = av[0], A1 = av[1], A2 = av[2], A3 = av[3];
        ulonglong2 A4 = av[4], A5 = av[5], A6 = av[6], A7 = av[7];

        float a0f = unpack2(A0.x).x;
        float rM  = frcp(a0f);

        unsigned long long acc0 = fma2(E2[0], A0.x, 0ull);
        unsigned long long acc1 = fma2(E2[1], A0.y, 0ull);
        unsigned long long acc2 = fma2(E2[2], A1.x, 0ull);
        unsigned long long acc3 = fma2(E2[3], A1.y, 0ull);
        acc0 = fma2(E2[4],  A2.x, acc0);
        acc1 = fma2(E2[5],  A2.y, acc1);
        acc2 = fma2(E2[6],  A3.x, acc2);
        acc3 = fma2(E2[7],  A3.y, acc3);
        acc0 = fma2(E2[8],  A4.x, acc0);
        acc1 = fma2(E2[9],  A4.y, acc1);
        acc2 = fma2(E2[10], A5.x, acc2);
        acc3 = fma2(E2[11], A5.y, acc3);
        acc0 = fma2(E2[12], A6.x, acc0);
        acc1 = fma2(E2[13], A6.y, acc1);
        acc2 = fma2(E2[14], A7.x, acc2);
        acc3 = fma2(E2[15], A7.y, acc3);
        unsigned long long s2 = add2(add2(acc0, acc1), add2(acc2, acc3));
        float2 sp = unpack2(s2);
        float dot = sp.x + sp.y;
        dot += __shfl_xor_sync(0xffffffffu, dot, 1);

        union { unsigned long long u[16]; float f[32]; } V;
        {
            ulonglong2 D0 = dv[0], D1 = dv[1], D2 = dv[2], D3 = dv[3];
            ulonglong2 D4 = dv[4], D5 = dv[5], D6 = dv[6], D7 = dv[7];
            V.u[0]  = add2(T2[0],  D0.x);  V.u[1]  = add2(T2[1],  D0.y);
            V.u[2]  = add2(T2[2],  D1.x);  V.u[3]  = add2(T2[3],  D1.y);
            V.u[4]  = add2(T2[4],  D2.x);  V.u[5]  = add2(T2[5],  D2.y);
            V.u[6]  = add2(T2[6],  D3.x);  V.u[7]  = add2(T2[7],  D3.y);
            V.u[8]  = add2(T2[8],  D4.x);  V.u[9]  = add2(T2[9],  D4.y);
            V.u[10] = add2(T2[10], D5.x);  V.u[11] = add2(T2[11], D5.y);
            V.u[12] = add2(T2[12], D6.x);  V.u[13] = add2(T2[13], D6.y);
            V.u[14] = add2(T2[14], D7.x);  V.u[15] = add2(T2[15], D7.y);
        }

        float m0 = V.f[0], m1 = V.f[1], m2 = V.f[2], m3 = V.f[3];
#pragma unroll
        for (int k = 1; k < 8; k++) {
            m0 = fmaxf(m0, V.f[4 * k + 0]);
            m1 = fmaxf(m1, V.f[4 * k + 1]);
            m2 = fmaxf(m2, V.f[4 * k + 2]);
            m3 = fmaxf(m3, V.f[4 * k + 3]);
        }
        float Mh = fmaxf(fmaxf(m0, m1), fmaxf(m2, m3));
        float M  = fmaxf(Mh, __shfl_xor_sync(0xffffffffu, Mh, 1));

        if (h == 0) {
            float lin = ef0 * dot;
            a_buf[p ^ 1][j] = (t == 0) ? lin : lin * rM;
            d_buf[p ^ 1][j] = M + f0;
        }
        __syncthreads();

        // trailing work (hides under next step's issue stream)
        unsigned msk0 = 0, msk1 = 0, msk2 = 0, msk3 = 0;
#pragma unroll
        for (int k = 0; k < 8; k++) {
            msk0 |= (V.f[4 * k + 0] == M) ? (1u << (4 * k + 0)) : 0u;
            msk1 |= (V.f[4 * k + 1] == M) ? (1u << (4 * k + 1)) : 0u;
            msk2 |= (V.f[4 * k + 2] == M) ? (1u << (4 * k + 2)) : 0u;
            msk3 |= (V.f[4 * k + 3] == M) ? (1u << (4 * k + 3)) : 0u;
        }
        unsigned msk = (msk0 | msk1) | (msk2 | msk3);
        int cand = msk ? (h * 32 + __ffs(msk) - 1) : 1000;
        int oc = __shfl_xor_sync(0xffffffffu, cand, 1);
        cand = min(cand, oc);
        if (h == 0) {
            int b2 = (t == 0) ? cand : (int)cs[(t - 1) & 1][cand];
            cs[t & 1][j] = (unsigned char)cand;
            bpb[(size_t)t * KK + j] = (unsigned short)(cand | (b2 << 8));
            if (t > 0) logscale += __logf(a0f);
        }
        p ^= 1;
        f0 = f1; f1 = f2; f2 = f3;
        ef0 = ef1; ef1 = ef2; ef2 = __expf(f3);
    }

    if (tid < 64) {
        const int* btags = tags + (size_t)b * TT;
        float g = 0.0f;
        for (int t = tid; t < TT; t += 64) {
            int tag  = btags[t];
            int prev = t ? btags[t - 1] : START;
            g += trans[tag * KK + prev] + bf[(size_t)t * KK + tag];
        }
        gred[tid] = g;
        asm volatile("bar.sync 4, 64;" ::: "memory");
        if (tid == 0) {
            float gold = 0.0f;
            for (int i = 0; i < 64; i++) gold += gred[i];
            gold += tStop[btags[TT - 1]];
            float s = 0.0f;
            for (int i = 0; i < KK; i++) s += a_buf[p][i] * __expf(tStop[i]);
            out[b] = (logscale + __logf(s)) - gold;
        }
    } else {
        int cur = 0;
        float* po = out + 2 * BB + (size_t)b * TT;
        if (tid == 64) {
            float best = -3.0e38f; int bl = 0;
            for (int i = 0; i < KK; i++) {
                float v = d_buf[p][i] + tStop[i];
                if (v > best) { best = v; bl = i; }
            }
            out[BB + b] = best;
            cur = bl;
            po[TT - 1] = (float)cur;
        }
        {
            const uint4* src = (const uint4*)(bpb + (size_t)31 * 128 * KK);
            uint4* dst = (uint4*)stage[1];
            for (int i = tid - 64; i < 1024; i += 64) dst[i] = src[i];
        }
        asm volatile("bar.sync 3, 64;" ::: "memory");
        for (int c = 31; c >= 0; c--) {
            if (tid != 64 && c > 0) {
                const uint4* src = (const uint4*)(bpb + (size_t)(c - 1) * 128 * KK);
                uint4* dst = (uint4*)stage[(c - 1) & 1];
                for (int i = tid - 65; i < 1024; i += 63) dst[i] = src[i];
            }
            if (tid == 64) {
                const unsigned short* st = stage[c & 1];
#pragma unroll 4
                for (int tt = 127; tt >= 1; tt -= 2) {
                    unsigned w = st[tt * KK + cur];
                    int lo = w & 255, hi = w >> 8;
                    int gt = c * 128 + tt;
                    po[gt - 1] = (float)lo;
                    if (gt > 1) po[gt - 2] = (float)hi;
                    cur = hi;
                }
            }
            asm volatile("bar.sync 3, 64;" ::: "memory");
        }
    }
}

extern "C" void kernel_launch(void* const* d_in, const int* in_sizes, int n_in,
                              void* d_out, int out_size)
{
    const float* feats = (const float*)d_in[0];
    const int*   tags  = (const int*)d_in[1];
    const float* trans = (const float*)d_in[2];
    float* out = (float*)d_out;
    crf_kernel2<<<BB, 128>>>(feats, tags, trans, out);
}

// round 6
// speedup vs baseline: 1.1363x; 1.1363x over previous
#include <cuda_runtime.h>
#include <cstdint>

#define BB 128
#define TT 4096
#define KK 64
#define START 62
#define STOP 63
#define NEGV -10000.0f

// packed backpointers: low byte = bp[t][j], high byte = bp[t-1][bp[t][j]]
__device__ unsigned short g_bp[(size_t)BB * TT * KK];   // 64 MB

__device__ __forceinline__ unsigned long long fma2(unsigned long long a, unsigned long long b, unsigned long long c) {
    unsigned long long d;
    asm("fma.rn.f32x2 %0, %1, %2, %3;" : "=l"(d) : "l"(a), "l"(b), "l"(c));
    return d;
}
__device__ __forceinline__ unsigned long long add2(unsigned long long a, unsigned long long b) {
    unsigned long long d;
    asm("add.rn.f32x2 %0, %1, %2;" : "=l"(d) : "l"(a), "l"(b));
    return d;
}
__device__ __forceinline__ unsigned long long pack2(float lo, float hi) {
    unsigned long long d;
    asm("mov.b64 %0, {%1, %2};" : "=l"(d) : "f"(lo), "f"(hi));
    return d;
}
__device__ __forceinline__ float2 unpack2(unsigned long long a) {
    float2 r;
    asm("mov.b64 {%0, %1}, %2;" : "=f"(r.x), "=f"(r.y) : "l"(a));
    return r;
}
__device__ __forceinline__ float frcp(float x) {
    float r; asm("rcp.approx.f32 %0, %1;" : "=f"(r) : "f"(x)); return r;
}
__device__ __forceinline__ void barF() { asm volatile("bar.sync 1, 128;" ::: "memory"); }
__device__ __forceinline__ void barV() { asm volatile("bar.sync 2, 128;" ::: "memory"); }

__global__ __launch_bounds__(256, 1)
void crf_kernel(const float* __restrict__ feats,
                const int*   __restrict__ tags,
                const float* __restrict__ trans,
                float*       __restrict__ out)
{
    __shared__ __align__(16) float a_buf[2][KK];
    __shared__ __align__(16) float d_buf[2][KK];
    __shared__ unsigned char cs[2][KK];
    __shared__ float tStop[KK];
    __shared__ float gred[64];
    __shared__ __align__(16) unsigned short stage[2][128 * KK];   // 2 x 16 KB

    const int b   = blockIdx.x;
    const int tid = threadIdx.x;
    const float* bf = feats + (size_t)b * TT * KK;
    unsigned short* bpb = g_bp + (size_t)b * TT * KK;
    int p = 0;
    float logscale = 0.0f;

    if (tid < 128) {
        // ================= FORWARD GROUP (warps 0-3), 2 threads/state =================
        const int j = tid >> 1;
        const int h = tid & 1;
        unsigned long long E2[16];
#pragma unroll
        for (int k = 0; k < 16; k++) {
            float t0 = trans[j * KK + h * 32 + 2 * k];
            float t1 = trans[j * KK + h * 32 + 2 * k + 1];
            E2[k] = pack2(__expf(t0), __expf(t1));
        }
        if (tid < KK) tStop[tid] = trans[STOP * KK + tid];
        if (h == 0) a_buf[0][j] = (j == START) ? 1.0f : 0.0f;

        // feats register queue, depth 6; exp queue depth 3
        float fq0 = bf[0 * KK + j], fq1 = bf[1 * KK + j], fq2 = bf[2 * KK + j];
        float fq3 = bf[3 * KK + j], fq4 = bf[4 * KK + j], fq5 = bf[5 * KK + j];
        float ef0 = __expf(fq0), ef1 = __expf(fq1), ef2 = __expf(fq2);
        barF();

        for (int t = 0; t < TT; t++) {
            float ld = (t + 6 < TT) ? bf[(size_t)(t + 6) * KK + j] : 0.0f;

            const ulonglong2* av = (const ulonglong2*)&a_buf[p][h * 32];
            ulonglong2 A0 = av[0], A1 = av[1], A2 = av[2], A3 = av[3];
            ulonglong2 A4 = av[4], A5 = av[5], A6 = av[6], A7 = av[7];

            float a0f = unpack2(A0.x).x;     // a_prev[first state of this half]
            float rM  = frcp(a0f);

            unsigned long long acc0 = fma2(E2[0], A0.x, 0ull);
            unsigned long long acc1 = fma2(E2[1], A0.y, 0ull);
            unsigned long long acc2 = fma2(E2[2], A1.x, 0ull);
            unsigned long long acc3 = fma2(E2[3], A1.y, 0ull);
            acc0 = fma2(E2[4],  A2.x, acc0);
            acc1 = fma2(E2[5],  A2.y, acc1);
            acc2 = fma2(E2[6],  A3.x, acc2);
            acc3 = fma2(E2[7],  A3.y, acc3);
            acc0 = fma2(E2[8],  A4.x, acc0);
            acc1 = fma2(E2[9],  A4.y, acc1);
            acc2 = fma2(E2[10], A5.x, acc2);
            acc3 = fma2(E2[11], A5.y, acc3);
            acc0 = fma2(E2[12], A6.x, acc0);
            acc1 = fma2(E2[13], A6.y, acc1);
            acc2 = fma2(E2[14], A7.x, acc2);
            acc3 = fma2(E2[15], A7.y, acc3);
            unsigned long long s2 = add2(add2(acc0, acc1), add2(acc2, acc3));
            float2 sp = unpack2(s2);
            float dot = sp.x + sp.y;
            dot += __shfl_xor_sync(0xffffffffu, dot, 1);

            if (h == 0) {
                float lin = ef0 * dot;
                a_buf[p ^ 1][j] = (t == 0) ? lin : lin * rM;
            }
            barF();

            // trailing (hidden under next step)
            if (tid == 0 && t > 0) logscale += __logf(a0f);
            float efn = __expf(fq3);
            fq0 = fq1; fq1 = fq2; fq2 = fq3; fq3 = fq4; fq4 = fq5; fq5 = ld;
            ef0 = ef1; ef1 = ef2; ef2 = efn;
            p ^= 1;
        }
    } else {
        // ================= VITERBI GROUP (warps 4-7), 2 threads/state =================
        const int vt = tid - 128;
        const int j = vt >> 1;
        const int h = vt & 1;
        unsigned long long T2[16];
#pragma unroll
        for (int k = 0; k < 16; k++) {
            float t0 = trans[j * KK + h * 32 + 2 * k];
            float t1 = trans[j * KK + h * 32 + 2 * k + 1];
            T2[k] = pack2(t0, t1);
        }
        if (h == 0) d_buf[0][j] = (j == START) ? 0.0f : NEGV;

        float fq0 = bf[0 * KK + j], fq1 = bf[1 * KK + j], fq2 = bf[2 * KK + j];
        float fq3 = bf[3 * KK + j], fq4 = bf[4 * KK + j], fq5 = bf[5 * KK + j];
        barV();

        for (int t = 0; t < TT; t++) {
            float ld = (t + 6 < TT) ? bf[(size_t)(t + 6) * KK + j] : 0.0f;

            const ulonglong2* dv = (const ulonglong2*)&d_buf[p][h * 32];
            union { unsigned long long u[16]; float f[32]; } V;
            {
                ulonglong2 D0 = dv[0], D1 = dv[1], D2 = dv[2], D3 = dv[3];
                ulonglong2 D4 = dv[4], D5 = dv[5], D6 = dv[6], D7 = dv[7];
                V.u[0]  = add2(T2[0],  D0.x);  V.u[1]  = add2(T2[1],  D0.y);
                V.u[2]  = add2(T2[2],  D1.x);  V.u[3]  = add2(T2[3],  D1.y);
                V.u[4]  = add2(T2[4],  D2.x);  V.u[5]  = add2(T2[5],  D2.y);
                V.u[6]  = add2(T2[6],  D3.x);  V.u[7]  = add2(T2[7],  D3.y);
                V.u[8]  = add2(T2[8],  D4.x);  V.u[9]  = add2(T2[9],  D4.y);
                V.u[10] = add2(T2[10], D5.x);  V.u[11] = add2(T2[11], D5.y);
                V.u[12] = add2(T2[12], D6.x);  V.u[13] = add2(T2[13], D6.y);
                V.u[14] = add2(T2[14], D7.x);  V.u[15] = add2(T2[15], D7.y);
            }

            float m0 = V.f[0], m1 = V.f[1], m2 = V.f[2], m3 = V.f[3];
#pragma unroll
            for (int k = 1; k < 8; k++) {
                m0 = fmaxf(m0, V.f[4 * k + 0]);
                m1 = fmaxf(m1, V.f[4 * k + 1]);
                m2 = fmaxf(m2, V.f[4 * k + 2]);
                m3 = fmaxf(m3, V.f[4 * k + 3]);
            }
            float Mh = fmaxf(fmaxf(m0, m1), fmaxf(m2, m3));
            float M  = fmaxf(Mh, __shfl_xor_sync(0xffffffffu, Mh, 1));

            if (h == 0) d_buf[p ^ 1][j] = M + fq0;
            barV();

            // trailing: argmax mask + composed backpointer store (hidden under next step)
            unsigned msk0 = 0, msk1 = 0, msk2 = 0, msk3 = 0;
#pragma unroll
            for (int k = 0; k < 8; k++) {
                msk0 |= (V.f[4 * k + 0] == M) ? (1u << (4 * k + 0)) : 0u;
                msk1 |= (V.f[4 * k + 1] == M) ? (1u << (4 * k + 1)) : 0u;
                msk2 |= (V.f[4 * k + 2] == M) ? (1u << (4 * k + 2)) : 0u;
                msk3 |= (V.f[4 * k + 3] == M) ? (1u << (4 * k + 3)) : 0u;
            }
            unsigned msk = (msk0 | msk1) | (msk2 | msk3);
            int cand = msk ? (h * 32 + __ffs(msk) - 1) : 1000;
            int oc = __shfl_xor_sync(0xffffffffu, cand, 1);
            cand = min(cand, oc);
            if (h == 0) {
                int b2 = (t == 0) ? cand : (int)cs[(t - 1) & 1][cand];
                cs[t & 1][j] = (unsigned char)cand;
                bpb[(size_t)t * KK + j] = (unsigned short)(cand | (b2 << 8));
            }
            fq0 = fq1; fq1 = fq2; fq2 = fq3; fq3 = fq4; fq4 = fq5; fq5 = ld;
            p ^= 1;
        }
    }

    __syncthreads();   // all 256 threads; a_buf/d_buf final parity p == 0

    if (tid < 64) {
        // ---- gold score + nll (warps 0-1) ----
        const int* btags = tags + (size_t)b * TT;
        float g = 0.0f;
        for (int t = tid; t < TT; t += 64) {
            int tag  = btags[t];
            int prev = t ? btags[t - 1] : START;
            g += trans[tag * KK + prev] + bf[(size_t)t * KK + tag];
        }
        gred[tid] = g;
        asm volatile("bar.sync 4, 64;" ::: "memory");
        if (tid == 0) {
            float gold = 0.0f;
            for (int i = 0; i < 64; i++) gold += gred[i];
            gold += tStop[btags[TT - 1]];
            float s = 0.0f;
            for (int i = 0; i < KK; i++) s += a_buf[p][i] * __expf(tStop[i]);
            out[b] = (logscale + __logf(s)) - gold;
        }
    } else if (tid < 128) {
        // ---- viterbi terminal + backtrack (warps 2-3) ----
        int cur = 0;
        float* po = out + 2 * BB + (size_t)b * TT;
        if (tid == 64) {
            float best = -3.0e38f; int bl = 0;
            for (int i = 0; i < KK; i++) {
                float v = d_buf[p][i] + tStop[i];
                if (v > best) { best = v; bl = i; }
            }
            out[BB + b] = best;
            cur = bl;
            po[TT - 1] = (float)cur;
        }
        // preload chunk 31 into stage[1]
        {
            const uint4* src = (const uint4*)(bpb + (size_t)31 * 128 * KK);
            uint4* dst = (uint4*)stage[1];
            for (int i = tid - 64; i < 1024; i += 64) dst[i] = src[i];
        }
        asm volatile("bar.sync 3, 64;" ::: "memory");
        for (int c = 31; c >= 0; c--) {
            if (tid != 64 && c > 0) {
                const uint4* src = (const uint4*)(bpb + (size_t)(c - 1) * 128 * KK);
                uint4* dst = (uint4*)stage[(c - 1) & 1];
                for (int i = tid - 65; i < 1024; i += 63) dst[i] = src[i];
            }
            if (tid == 64) {
                const unsigned short* st = stage[c & 1];
#pragma unroll 4
                for (int tt = 127; tt >= 1; tt -= 2) {
                    unsigned w = st[tt * KK + cur];
                    int lo = w & 255, hi = w >> 8;
                    int gt = c * 128 + tt;
                    po[gt - 1] = (float)lo;
                    if (gt > 1) po[gt - 2] = (float)hi;
                    cur = hi;
                }
            }
            asm volatile("bar.sync 3, 64;" ::: "memory");
        }
    }
}

extern "C" void kernel_launch(void* const* d_in, const int* in_sizes, int n_in,
                              void* d_out, int out_size)
{
    const float* feats = (const float*)d_in[0];
    const int*   tags  = (const int*)d_in[1];
    const float* trans = (const float*)d_in[2];
    float* out = (float*)d_out;
    crf_kernel<<<BB, 256>>>(feats, tags, trans, out);
}